// round 8
// baseline (speedup 1.0000x reference)
#include <cuda_runtime.h>
#include <cuda_bf16.h>
#include <cstdint>

// AbsDiff cost volume:
//   out[n, d, y, x] = |image1[n,0,y,x] - image2[n,0,y,x-d]|  if x-d >= 0 else 0
// in [2,1,384,1248] fp32, out [2,128,384,1248] fp32. HBM-write-bound (~491MB).
// R8: route the output stream around the L1tex store path. Each CTA computes
// 8 full output rows (4992B each) into smem, then ONE thread issues 8
// cp.async.bulk.global.shared (TMA bulk store) copies; the TMA engine feeds
// L2/DRAM directly. Tests whether L1tex wavefront delivery (74-76% in every
// prior variant) was co-binding with DRAM (stuck at ~80%).

#define W_DIM    1248
#define H_DIM    384
#define N_DIM    2
#define D_DIM    128
#define W4       (W_DIM / 4)          // 312
#define THREADS  320                  // 10 warps; 312 active in compute
#define D_CHUNK  8                    // d0 = 8*blockIdx.y
#define ROW_B    (W_DIM * 4)          // 4992 bytes, multiple of 16

__device__ __forceinline__ uint32_t smem_u32(const void* p) {
    uint32_t a;
    asm("{ .reg .u64 t; cvta.to.shared.u64 t, %1; cvt.u32.u64 %0, t; }"
        : "=r"(a) : "l"(p));
    return a;
}

__global__ __launch_bounds__(THREADS, 5)
void absdiff_costvol_kernel(const float* __restrict__ left,
                            const float* __restrict__ right,
                            float* __restrict__ out)
{
    __shared__ __align__(16) float sl[D_CHUNK][W_DIM];   // 39936 B

    const int nh = blockIdx.x;                 // n*H + y   (768)
    const int d0 = blockIdx.y * D_CHUNK;       // multiple of 8
    const int t  = threadIdx.x;

    if (t < W4) {
        const int x0 = 4 * t;

        const float4 L = reinterpret_cast<const float4*>(
                             left + (size_t)nh * W_DIM)[t];

        // 12-float shifted window from the right row: float4 blocks b..b+2,
        // covering floats [x0-d0-8, x0-d0+3]. Negative blocks clamp to 0 —
        // clamped values feed only mask-zeroed outputs (x < d).
        const float4* rrow4 = reinterpret_cast<const float4*>(
                                  right + (size_t)nh * W_DIM);
        const int b  = t - d0 / 4 - 2;
        const int b0 = b     < 0 ? 0 : b;
        const int b1 = b + 1 < 0 ? 0 : b + 1;
        const int b2 = b + 2 < 0 ? 0 : b + 2;

        float w[12];
        {
            const float4 X = rrow4[b0];
            const float4 Y = rrow4[b1];
            const float4 Z = rrow4[b2];
            w[0]=X.x; w[1]=X.y; w[2]=X.z;  w[3]=X.w;
            w[4]=Y.x; w[5]=Y.y; w[6]=Y.z;  w[7]=Y.w;
            w[8]=Z.x; w[9]=Z.y; w[10]=Z.z; w[11]=Z.w;
        }

        #pragma unroll
        for (int k = 0; k < D_CHUNK; ++k) {
            const int d  = d0 + k;
            const int j0 = 8 - k;              // compile-time window offset

            float4 v;
            v.x = (x0 + 0 >= d) ? fabsf(L.x - w[j0 + 0]) : 0.f;
            v.y = (x0 + 1 >= d) ? fabsf(L.y - w[j0 + 1]) : 0.f;
            v.z = (x0 + 2 >= d) ? fabsf(L.z - w[j0 + 2]) : 0.f;
            v.w = (x0 + 3 >= d) ? fabsf(L.w - w[j0 + 3]) : 0.f;

            reinterpret_cast<float4*>(sl[k])[t] = v;   // STS.128
        }
    }

    __syncthreads();

    // One thread drains the CTA's 8 rows via TMA bulk stores.
    if (t == 0) {
        asm volatile("fence.proxy.async.shared::cta;" ::: "memory");

        const int n = nh / H_DIM;
        const int y = nh % H_DIM;
        float* ob = out + ((size_t)(n * D_DIM + d0) * H_DIM + y) * W_DIM;

        #pragma unroll
        for (int k = 0; k < D_CHUNK; ++k) {
            const uint32_t src = smem_u32(sl[k]);
            float* dst = ob + (size_t)k * (H_DIM * W_DIM);
            asm volatile(
                "cp.async.bulk.global.shared::cta.bulk_group [%0], [%1], %2;"
                :: "l"(dst), "r"(src), "n"(ROW_B) : "memory");
        }
        asm volatile("cp.async.bulk.commit_group;" ::: "memory");
        // Keep smem alive until the TMA engine has read it.
        asm volatile("cp.async.bulk.wait_group.read 0;" ::: "memory");
    }
}

extern "C" void kernel_launch(void* const* d_in, const int* in_sizes, int n_in,
                              void* d_out, int out_size)
{
    const float* image1 = (const float*)d_in[0];  // left
    const float* image2 = (const float*)d_in[1];  // right (shifted source)
    float* out = (float*)d_out;

    (void)in_sizes; (void)n_in; (void)out_size;

    dim3 grid(N_DIM * H_DIM, D_DIM / D_CHUNK);   // 768 x 16 = 12288 blocks
    dim3 block(THREADS);
    absdiff_costvol_kernel<<<grid, block>>>(image1, image2, out);
}

// round 10
// speedup vs baseline: 1.1173x; 1.1173x over previous
#include <cuda_runtime.h>
#include <cuda_bf16.h>
#include <cstdint>

// AbsDiff cost volume:
//   out[n, d, y, x] = |image1[n,0,y,x] - image2[n,0,y,x-d]|  if x-d >= 0 else 0
// in [2,1,384,1248] fp32, out [2,128,384,1248] fp32. HBM-write-bound (~491MB,
// 61.4us floor @ 8TB/s). R10 = R4 (smem-staged right row, one-shot 12-float
// register window, 8x STG.128 evict-first) + L2 policy partition: inputs
// loaded with createpolicy(evict_last) cache hint so the .cs write stream
// never evicts them. (R9 used the direct .L2::evict_last qualifier, which
// ptxas only allows on v8.b32/v4.b64 — cache_hint form works on v4.f32.)

#define W_DIM    1248
#define H_DIM    384
#define N_DIM    2
#define D_DIM    128
#define W4       (W_DIM / 4)          // 312
#define THREADS  320                  // 10 warps
#define D_SPLIT  16
#define D_CHUNK  (D_DIM / D_SPLIT)    // 8; d0 multiple of 8
#define PAD      128                  // leading zeros: x-d never underflows

__device__ __forceinline__ void stcs4(float4* p, float4 v) {
    asm volatile("st.global.cs.v4.f32 [%0], {%1,%2,%3,%4};"
                 :: "l"(p), "f"(v.x), "f"(v.y), "f"(v.z), "f"(v.w) : "memory");
}

__device__ __forceinline__ float4 ldg_keep4(const float4* p, uint64_t pol) {
    float4 v;
    asm volatile("ld.global.nc.L2::cache_hint.v4.f32 {%0,%1,%2,%3}, [%4], %5;"
                 : "=f"(v.x), "=f"(v.y), "=f"(v.z), "=f"(v.w)
                 : "l"(p), "l"(pol));
    return v;
}

__global__ __launch_bounds__(THREADS, 6)
void absdiff_costvol_kernel(const float* __restrict__ left,
                            const float* __restrict__ right,
                            float* __restrict__ out)
{
    __shared__ float4 sr4[(PAD + W_DIM) / 4];   // 344 float4 = 5.5 KB

    const int nh = blockIdx.x;                  // n*H + y   (768)
    const int d0 = blockIdx.y * D_CHUNK;        // multiple of 8
    const int t  = threadIdx.x;

    uint64_t pol;
    asm volatile("createpolicy.fractional.L2::evict_last.b64 %0, 1.0;"
                 : "=l"(pol));

    const float4* rrow4 = (const float4*)(right + (size_t)nh * W_DIM);
    const float4* lrow4 = (const float4*)(left  + (size_t)nh * W_DIM);

    // Stage: zeros in the pad, right row after it. Inputs tagged evict_last.
    if (t < PAD / 4)
        sr4[t] = make_float4(0.f, 0.f, 0.f, 0.f);
    float4 L = make_float4(0.f, 0.f, 0.f, 0.f);
    if (t < W4) {
        sr4[PAD / 4 + t] = ldg_keep4(rrow4 + t, pol);
        L = ldg_keep4(lrow4 + t, pol);
    }

    __syncthreads();

    const int n = nh / H_DIM;
    const int y = nh % H_DIM;
    float* ob = out + ((size_t)(n * D_DIM + d0) * H_DIM + y) * W_DIM;

    if (t < W4) {
        const int x0 = 4 * t;                   // first x this thread owns
        const int c0 = PAD - d0 + x0;           // smem float idx of R[x0-d0]; %4==0
        const int b4 = c0 >> 2;                 // >= 2 always

        // One-shot window load: floats [c0-8, c0+3] cover all 8 shifted reads.
        float w[12];
        {
            const float4 X = sr4[b4 - 2];
            const float4 Y = sr4[b4 - 1];
            const float4 Z = sr4[b4];
            w[0]=X.x; w[1]=X.y; w[2]=X.z;  w[3]=X.w;
            w[4]=Y.x; w[5]=Y.y; w[6]=Y.z;  w[7]=Y.w;
            w[8]=Z.x; w[9]=Z.y; w[10]=Z.z; w[11]=Z.w;
        }

        #pragma unroll
        for (int k = 0; k < D_CHUNK; ++k) {
            const int d  = d0 + k;
            const int j0 = 8 - k;               // compile-time window offset

            float4 v;
            v.x = (x0 + 0 >= d) ? fabsf(L.x - w[j0 + 0]) : 0.f;
            v.y = (x0 + 1 >= d) ? fabsf(L.y - w[j0 + 1]) : 0.f;
            v.z = (x0 + 2 >= d) ? fabsf(L.z - w[j0 + 2]) : 0.f;
            v.w = (x0 + 3 >= d) ? fabsf(L.w - w[j0 + 3]) : 0.f;

            stcs4((float4*)(ob + (size_t)k * (H_DIM * W_DIM)) + t, v);
        }
    }
}

extern "C" void kernel_launch(void* const* d_in, const int* in_sizes, int n_in,
                              void* d_out, int out_size)
{
    const float* image1 = (const float*)d_in[0];  // left
    const float* image2 = (const float*)d_in[1];  // right (shifted source)
    float* out = (float*)d_out;

    (void)in_sizes; (void)n_in; (void)out_size;

    dim3 grid(N_DIM * H_DIM, D_SPLIT);   // 768 x 16 = 12288 blocks
    dim3 block(THREADS);
    absdiff_costvol_kernel<<<grid, block>>>(image1, image2, out);
}